// round 2
// baseline (speedup 1.0000x reference)
#include <cuda_runtime.h>
#include <cuda_bf16.h>
#include <cstddef>

#define N_NODES 100000
#define N_EDGES 1200000
#define HID 64
#define F_IN 16
#define G_GRAPHS 1024
#define ROWS 80            // 100000 % 80 == 0 -> 1250 blocks, no row guards
#define WTS 68             // sWt row stride (padded to kill bank conflicts)

// ---------------- scratch (device globals; no allocation) ----------------
__device__ float g_aggr[(size_t)N_NODES * HID];
__device__ float g_h1 [(size_t)N_NODES * HID];
__device__ float g_h2 [(size_t)N_NODES * HID];
__device__ float g_stats[3][2 * HID];          // per layer: [0:64) sum, [64:128) sumsq
__device__ float g_pool[(size_t)G_GRAPHS * HID];
__device__ float g_cnt [G_GRAPHS];

// packed fp32x2 FMA (Blackwell): d = a*b + c elementwise on 2 packed floats
__device__ __forceinline__ unsigned long long fma2_(unsigned long long a,
                                                    unsigned long long b,
                                                    unsigned long long c) {
    unsigned long long d;
    asm("fma.rn.f32x2 %0, %1, %2, %3;" : "=l"(d) : "l"(a), "l"(b), "l"(c));
    return d;
}

union U64F2 { unsigned long long u; float2 f; };

// BN scale/shift from accumulated sum/sumsq (training-mode batch stats)
__device__ __forceinline__ void bn_coeffs(const float* __restrict__ stats,
                                          const float* __restrict__ gamma,
                                          const float* __restrict__ beta,
                                          float* sc, float* sh) {
    int t = threadIdx.x;
    if (t < HID) {
        const float invN = 1.0f / (float)N_NODES;
        float mean = stats[t] * invN;
        float var  = stats[HID + t] * invN - mean * mean;
        float s    = gamma[t] * rsqrtf(var + 1e-5f);
        sc[t] = s;
        sh[t] = beta[t] - mean * s;
    }
}

// ---------------- zero pass (layer-1 aggr region + stats + pool) ----------------
__global__ void zero_misc_kernel() {
    int i = blockIdx.x * blockDim.x + threadIdx.x;
    if (i < N_NODES * F_IN)  g_aggr[i] = 0.0f;
    if (i < 3 * 2 * HID)     ((float*)g_stats)[i] = 0.0f;
    if (i < G_GRAPHS * HID)  g_pool[i] = 0.0f;
    if (i < G_GRAPHS)        g_cnt[i]  = 0.0f;
}

// ---------------- layer-1 scatter (16-wide, raw x) ----------------
__global__ __launch_bounds__(256)
void scatter16_kernel(const float* __restrict__ x,
                      const int* __restrict__ src,
                      const int* __restrict__ dst) {
    int idx = blockIdx.x * blockDim.x + threadIdx.x;
    if (idx >= N_EDGES * 4) return;
    int e = idx >> 2, q = idx & 3;
    int s = src[e], d = dst[e];
    float4 v = reinterpret_cast<const float4*>(x + (size_t)s * F_IN)[q];
    atomicAdd(reinterpret_cast<float4*>(g_aggr + (size_t)d * F_IN) + q, v);
}

// ---------------- 64-wide scatter with BN applied inline ----------------
__global__ __launch_bounds__(256)
void scatter_bn_kernel(const float* __restrict__ h,
                       const int* __restrict__ src,
                       const int* __restrict__ dst,
                       const float* __restrict__ stats,
                       const float* __restrict__ gamma,
                       const float* __restrict__ beta) {
    __shared__ float sc[HID], sh[HID];
    bn_coeffs(stats, gamma, beta, sc, sh);
    __syncthreads();
    int idx = blockIdx.x * blockDim.x + threadIdx.x;
    if (idx >= N_EDGES * 16) return;
    int e = idx >> 4, q = idx & 15;
    int s = src[e], d = dst[e];
    float4 v = reinterpret_cast<const float4*>(h + (size_t)s * HID)[q];
    int f = q * 4;
    v.x = v.x * sc[f    ] + sh[f    ];
    v.y = v.y * sc[f + 1] + sh[f + 1];
    v.z = v.z * sc[f + 2] + sh[f + 2];
    v.w = v.w * sc[f + 3] + sh[f + 3];
    atomicAdd(reinterpret_cast<float4*>(g_aggr + (size_t)d * HID) + q, v);
}

// ---------------- GEMM [N,K]@[K,64] + bias + ReLU, packed f32x2 over K ----------------
// AGGR : input = (1+eps)*X' + g_aggr  (X' = BN(X) if BNIN else X)
// STATS: accumulate per-column sum/sumsq of output into stats_out
// ZEROA: zero g_aggr over this block's [row,col] region (for next layer)
template <int K, bool AGGR, bool BNIN, bool STATS, bool ZEROA>
__global__ __launch_bounds__(256)
void gemm_kernel(const float* __restrict__ X,
                 const float* __restrict__ W,
                 const float* __restrict__ bias,
                 const float* __restrict__ eps_p,
                 const float* __restrict__ stats,
                 const float* __restrict__ gamma,
                 const float* __restrict__ beta,
                 float* __restrict__ out,
                 float* __restrict__ stats_out) {
    __shared__ float sWt[64 * WTS];          // transposed weights [col][k], padded
    __shared__ float sIn[ROWS * K];
    __shared__ float sc[HID], sh[HID];
    __shared__ float sSum[HID], sSq[HID];

    const int tid = threadIdx.x;             // 256 threads
    const int c   = tid & 15;                // col group of 4 (cols c*4..c*4+3)
    const int rg  = tid >> 4;                // 0..15; rows rg + 16*r, r<5
    const size_t row0 = (size_t)blockIdx.x * ROWS;

    if (BNIN) bn_coeffs(stats, gamma, beta, sc, sh);
    if (STATS && tid < HID) { sSum[tid] = 0.0f; sSq[tid] = 0.0f; }

    // transpose W into sWt[col][k]
    for (int i = tid; i < K * 64; i += 256) {
        int k = i >> 6, col = i & 63;
        sWt[col * WTS + k] = W[i];
    }
    __syncthreads();                          // sc/sh ready for sIn load

    float epsv = 1.0f;
    if (AGGR) epsv = 1.0f + *eps_p;
    for (int i = tid; i < ROWS * K; i += 256) {
        size_t gi = row0 * K + i;
        float v = X[gi];
        if (BNIN) { int f = i & (K - 1); v = v * sc[f] + sh[f]; }
        if (AGGR) v = epsv * v + g_aggr[gi];
        sIn[i] = v;
    }
    __syncthreads();

    unsigned long long acc[5][4];             // [row][col], halves = even/odd-k sums
#pragma unroll
    for (int r = 0; r < 5; r++)
#pragma unroll
        for (int cc = 0; cc < 4; cc++) acc[r][cc] = 0ull;

#pragma unroll 2
    for (int k = 0; k < K; k += 4) {
        ulonglong2 w[4];
#pragma unroll
        for (int cc = 0; cc < 4; cc++)
            w[cc] = *reinterpret_cast<const ulonglong2*>(&sWt[(c * 4 + cc) * WTS + k]);
#pragma unroll
        for (int r = 0; r < 5; r++) {
            ulonglong2 a = *reinterpret_cast<const ulonglong2*>(&sIn[(rg + 16 * r) * K + k]);
#pragma unroll
            for (int cc = 0; cc < 4; cc++) {
                acc[r][cc] = fma2_(a.x, w[cc].x, acc[r][cc]);
                acc[r][cc] = fma2_(a.y, w[cc].y, acc[r][cc]);
            }
        }
    }

    // epilogue: reduce halves, bias, relu, store (+stats, +zero aggr)
    const float4 bv = reinterpret_cast<const float4*>(bias)[c];
    float ls[4] = {0, 0, 0, 0}, lss[4] = {0, 0, 0, 0};
#pragma unroll
    for (int r = 0; r < 5; r++) {
        size_t row = row0 + rg + 16 * r;
        float o[4];
#pragma unroll
        for (int cc = 0; cc < 4; cc++) {
            U64F2 u; u.u = acc[r][cc];
            float b = (cc == 0) ? bv.x : (cc == 1) ? bv.y : (cc == 2) ? bv.z : bv.w;
            o[cc] = fmaxf(u.f.x + u.f.y + b, 0.0f);
            if (STATS) { ls[cc] += o[cc]; lss[cc] += o[cc] * o[cc]; }
        }
        float4 ov = make_float4(o[0], o[1], o[2], o[3]);
        reinterpret_cast<float4*>(out + row * 64)[c] = ov;
        if (ZEROA)
            reinterpret_cast<float4*>(g_aggr + row * 64)[c] = make_float4(0, 0, 0, 0);
    }

    if (STATS) {
#pragma unroll
        for (int cc = 0; cc < 4; cc++) {
            atomicAdd(&sSum[c * 4 + cc], ls[cc]);
            atomicAdd(&sSq[c * 4 + cc],  lss[cc]);
        }
        __syncthreads();
        if (tid < HID) {
            atomicAdd(&stats_out[tid],       sSum[tid]);
            atomicAdd(&stats_out[HID + tid], sSq[tid]);
        }
    }
}

// ---------------- pool with final BN fused ----------------
__global__ __launch_bounds__(256)
void pool_bn_kernel(const float* __restrict__ h,
                    const int* __restrict__ batch,
                    const float* __restrict__ stats,
                    const float* __restrict__ gamma,
                    const float* __restrict__ beta) {
    __shared__ float sc[HID], sh[HID];
    bn_coeffs(stats, gamma, beta, sc, sh);
    __syncthreads();
    int idx = blockIdx.x * blockDim.x + threadIdx.x;
    if (idx >= N_NODES * 16) return;
    int n = idx >> 4, q = idx & 15;
    int g = batch[n];
    float4 v = reinterpret_cast<const float4*>(h)[idx];
    int f = q * 4;
    v.x = v.x * sc[f    ] + sh[f    ];
    v.y = v.y * sc[f + 1] + sh[f + 1];
    v.z = v.z * sc[f + 2] + sh[f + 2];
    v.w = v.w * sc[f + 3] + sh[f + 3];
    atomicAdd(reinterpret_cast<float4*>(g_pool) + (size_t)g * 16 + q, v);
    if (q == 0) atomicAdd(&g_cnt[g], 1.0f);
}

// ---------------- readout MLP: mean -> [64,10] relu -> [10,1] ----------------
__global__ void readout_kernel(const float* __restrict__ Wf1,
                               const float* __restrict__ bf1,
                               const float* __restrict__ Wf2,
                               const float* __restrict__ bf2,
                               float* __restrict__ out) {
    int g = blockIdx.x * blockDim.x + threadIdx.x;
    if (g >= G_GRAPHS) return;
    float inv = 1.0f / fmaxf(g_cnt[g], 1.0f);
    float hid[10];
#pragma unroll
    for (int j = 0; j < 10; j++) hid[j] = bf1[j];
    for (int k = 0; k < 64; k++) {
        float p = g_pool[(size_t)g * 64 + k] * inv;
#pragma unroll
        for (int j = 0; j < 10; j++) hid[j] += p * Wf1[k * 10 + j];
    }
    float o = bf2[0];
#pragma unroll
    for (int j = 0; j < 10; j++) o += fmaxf(hid[j], 0.0f) * Wf2[j];
    out[g] = o;
}

// ---------------- host launcher ----------------
static inline int cdiv(long long a, int b) { return (int)((a + b - 1) / b); }

extern "C" void kernel_launch(void* const* d_in, const int* in_sizes, int n_in,
                              void* d_out, int out_size) {
    (void)in_sizes; (void)n_in; (void)out_size;
    const float* x     = (const float*)d_in[0];
    const int*   ei    = (const int*)  d_in[1];
    const int*   batch = (const int*)  d_in[2];
    const float* W1a = (const float*)d_in[3];  const float* b1a = (const float*)d_in[4];
    const float* W1b = (const float*)d_in[5];  const float* b1b = (const float*)d_in[6];
    const float* e1  = (const float*)d_in[7];
    const float* g1  = (const float*)d_in[8];  const float* be1 = (const float*)d_in[9];
    const float* W2a = (const float*)d_in[10]; const float* b2a = (const float*)d_in[11];
    const float* W2b = (const float*)d_in[12]; const float* b2b = (const float*)d_in[13];
    const float* e2  = (const float*)d_in[14];
    const float* g2  = (const float*)d_in[15]; const float* be2 = (const float*)d_in[16];
    const float* W3a = (const float*)d_in[17]; const float* b3a = (const float*)d_in[18];
    const float* W3b = (const float*)d_in[19]; const float* b3b = (const float*)d_in[20];
    const float* e3  = (const float*)d_in[21];
    const float* g3  = (const float*)d_in[22]; const float* be3 = (const float*)d_in[23];
    const float* Wf1 = (const float*)d_in[24]; const float* bf1 = (const float*)d_in[25];
    const float* Wf2 = (const float*)d_in[26]; const float* bf2 = (const float*)d_in[27];
    float* out = (float*)d_out;

    const int* src = ei;
    const int* dst = ei + N_EDGES;

    void *p_h1, *p_h2, *p_stats;
    cudaGetSymbolAddress(&p_h1, g_h1);
    cudaGetSymbolAddress(&p_h2, g_h2);
    cudaGetSymbolAddress(&p_stats, g_stats);
    float* h1 = (float*)p_h1;
    float* h2 = (float*)p_h2;
    float* st0 = (float*)p_stats;
    float* st1 = st0 + 2 * HID;
    float* st2 = st0 + 4 * HID;

    const int TB = 256;
    const int GB = N_NODES / ROWS;   // 1250

    zero_misc_kernel<<<cdiv(N_NODES * F_IN, TB), TB>>>();

    // ===== layer 1 =====
    scatter16_kernel<<<cdiv((long long)N_EDGES * 4, TB), TB>>>(x, src, dst);
    gemm_kernel<F_IN, true,  false, false, false><<<GB, TB>>>(x,  W1a, b1a, e1, nullptr, nullptr, nullptr, h1, nullptr);
    gemm_kernel<HID,  false, false, true,  true ><<<GB, TB>>>(h1, W1b, b1b, nullptr, nullptr, nullptr, nullptr, h2, st0);

    // ===== layer 2 =====
    scatter_bn_kernel<<<cdiv((long long)N_EDGES * 16, TB), TB>>>(h2, src, dst, st0, g1, be1);
    gemm_kernel<HID, true,  true,  false, false><<<GB, TB>>>(h2, W2a, b2a, e2, st0, g1, be1, h1, nullptr);
    gemm_kernel<HID, false, false, true,  true ><<<GB, TB>>>(h1, W2b, b2b, nullptr, nullptr, nullptr, nullptr, h2, st1);

    // ===== layer 3 =====
    scatter_bn_kernel<<<cdiv((long long)N_EDGES * 16, TB), TB>>>(h2, src, dst, st1, g2, be2);
    gemm_kernel<HID, true,  true,  false, false><<<GB, TB>>>(h2, W3a, b3a, e3, st1, g2, be2, h1, nullptr);
    gemm_kernel<HID, false, false, true,  false><<<GB, TB>>>(h1, W3b, b3b, nullptr, nullptr, nullptr, nullptr, h2, st2);

    // ===== pool + readout (BN3 fused into pool) =====
    pool_bn_kernel<<<cdiv(N_NODES * 16, TB), TB>>>(h2, batch, st2, g3, be3);
    readout_kernel<<<cdiv(G_GRAPHS, TB), TB>>>(Wf1, bf1, Wf2, bf2, out);
}

// round 3
// speedup vs baseline: 1.4896x; 1.4896x over previous
#include <cuda_runtime.h>
#include <cuda_bf16.h>
#include <cstddef>

#define N_NODES 100000
#define N_EDGES 1200000
#define HID 64
#define F_IN 16
#define G_GRAPHS 1024
#define TROWS 128          // rows per block tile (8 per thread * 16 row-groups)

// ---------------- scratch (device globals; no allocation) ----------------
__device__ float g_aggr[(size_t)N_NODES * HID];
__device__ float g_h1 [(size_t)N_NODES * HID];
__device__ float g_h2 [(size_t)N_NODES * HID];
__device__ float g_stats[3][2 * HID];          // per layer: [0:64) sum, [64:128) sumsq
__device__ float g_pool[(size_t)G_GRAPHS * HID];
__device__ float g_cnt [G_GRAPHS];

// BN scale/shift from accumulated sum/sumsq (training-mode batch stats)
__device__ __forceinline__ void bn_coeffs(const float* __restrict__ stats,
                                          const float* __restrict__ gamma,
                                          const float* __restrict__ beta,
                                          float* sc, float* sh) {
    int t = threadIdx.x;
    if (t < HID) {
        const float invN = 1.0f / (float)N_NODES;
        float mean = stats[t] * invN;
        float var  = stats[HID + t] * invN - mean * mean;
        float s    = gamma[t] * rsqrtf(var + 1e-5f);
        sc[t] = s;
        sh[t] = beta[t] - mean * s;
    }
}

// ---------------- zero pass (layer-1 aggr region + stats + pool) ----------------
__global__ void zero_misc_kernel() {
    int i = blockIdx.x * blockDim.x + threadIdx.x;
    if (i < N_NODES * F_IN)  g_aggr[i] = 0.0f;
    if (i < 3 * 2 * HID)     ((float*)g_stats)[i] = 0.0f;
    if (i < G_GRAPHS * HID)  g_pool[i] = 0.0f;
    if (i < G_GRAPHS)        g_cnt[i]  = 0.0f;
}

// ---------------- layer-1 scatter (16-wide, raw x) ----------------
__global__ __launch_bounds__(256)
void scatter16_kernel(const float* __restrict__ x,
                      const int* __restrict__ src,
                      const int* __restrict__ dst) {
    int idx = blockIdx.x * blockDim.x + threadIdx.x;
    if (idx >= N_EDGES * 4) return;
    int e = idx >> 2, q = idx & 3;
    int s = src[e], d = dst[e];
    float4 v = reinterpret_cast<const float4*>(x + (size_t)s * F_IN)[q];
    atomicAdd(reinterpret_cast<float4*>(g_aggr + (size_t)d * F_IN) + q, v);
}

// ---------------- 64-wide scatter with BN applied inline ----------------
__global__ __launch_bounds__(256)
void scatter_bn_kernel(const float* __restrict__ h,
                       const int* __restrict__ src,
                       const int* __restrict__ dst,
                       const float* __restrict__ stats,
                       const float* __restrict__ gamma,
                       const float* __restrict__ beta) {
    __shared__ float sc[HID], sh[HID];
    bn_coeffs(stats, gamma, beta, sc, sh);
    __syncthreads();
    int idx = blockIdx.x * blockDim.x + threadIdx.x;
    if (idx >= N_EDGES * 16) return;
    int e = idx >> 4, q = idx & 15;
    int s = src[e], d = dst[e];
    float4 v = reinterpret_cast<const float4*>(h + (size_t)s * HID)[q];
    int f = q * 4;
    v.x = v.x * sc[f    ] + sh[f    ];
    v.y = v.y * sc[f + 1] + sh[f + 1];
    v.z = v.z * sc[f + 2] + sh[f + 2];
    v.w = v.w * sc[f + 3] + sh[f + 3];
    atomicAdd(reinterpret_cast<float4*>(g_aggr + (size_t)d * HID) + q, v);
}

// ---------------- GEMM [N,K]@[K,64] + bias + ReLU ----------------
// 256 threads, tile 128 rows x 64 cols, 8 rows x 4 cols per thread,
// k-vectorized by 4 (LDS.128 everywhere, conflict-free / broadcast).
// AGGR : input = (1+eps)*X' + g_aggr  (X' = BN(X) if BNIN else X)
// STATS: accumulate per-column sum/sumsq of output into stats_out
// ZEROA: zero g_aggr over this block's [row, 0..64) region (for next layer)
template <int K, bool AGGR, bool BNIN, bool STATS, bool ZEROA>
__global__ __launch_bounds__(256)
void gemm_kernel(const float* __restrict__ X,
                 const float* __restrict__ W,
                 const float* __restrict__ bias,
                 const float* __restrict__ eps_p,
                 const float* __restrict__ stats,
                 const float* __restrict__ gamma,
                 const float* __restrict__ beta,
                 float* __restrict__ out,
                 float* __restrict__ stats_out) {
    __shared__ float sW[K * 64];              // natural [k][col] layout
    __shared__ float sIn[TROWS * K];          // [row][k]
    __shared__ float sc[HID], sh[HID];
    __shared__ float sSum[HID], sSq[HID];

    const int tid = threadIdx.x;              // 256 threads
    const int tx  = tid & 15;                 // col group: cols tx*4 .. tx*4+3
    const int ty  = tid >> 4;                 // row group: rows ty*8 .. ty*8+7
    const size_t row0 = (size_t)blockIdx.x * TROWS;

    if (BNIN) bn_coeffs(stats, gamma, beta, sc, sh);
    if (STATS && tid < HID) { sSum[tid] = 0.0f; sSq[tid] = 0.0f; }

    for (int i = tid; i < K * 64; i += 256) sW[i] = W[i];
    __syncthreads();                          // sc/sh ready before sIn load

    float epsv = 1.0f;
    if (AGGR) epsv = 1.0f + *eps_p;
    for (int i = tid; i < TROWS * K; i += 256) {
        size_t r = row0 + (size_t)(i / K);
        float v = 0.0f;
        if (r < N_NODES) {
            size_t gi = row0 * K + i;
            v = X[gi];
            if (BNIN) { int f = i & (K - 1); v = v * sc[f] + sh[f]; }
            if (AGGR) v = epsv * v + g_aggr[gi];
        }
        sIn[i] = v;
    }
    __syncthreads();

    float4 acc[8];
#pragma unroll
    for (int j = 0; j < 8; j++) acc[j] = make_float4(0, 0, 0, 0);

#pragma unroll
    for (int k = 0; k < K; k += 4) {
        float4 w0 = *reinterpret_cast<const float4*>(&sW[(k + 0) * 64 + tx * 4]);
        float4 w1 = *reinterpret_cast<const float4*>(&sW[(k + 1) * 64 + tx * 4]);
        float4 w2 = *reinterpret_cast<const float4*>(&sW[(k + 2) * 64 + tx * 4]);
        float4 w3 = *reinterpret_cast<const float4*>(&sW[(k + 3) * 64 + tx * 4]);
#pragma unroll
        for (int j = 0; j < 8; j++) {
            float4 a = *reinterpret_cast<const float4*>(&sIn[(ty * 8 + j) * K + k]);
            acc[j].x = fmaf(a.x, w0.x, acc[j].x);
            acc[j].y = fmaf(a.x, w0.y, acc[j].y);
            acc[j].z = fmaf(a.x, w0.z, acc[j].z);
            acc[j].w = fmaf(a.x, w0.w, acc[j].w);
            acc[j].x = fmaf(a.y, w1.x, acc[j].x);
            acc[j].y = fmaf(a.y, w1.y, acc[j].y);
            acc[j].z = fmaf(a.y, w1.z, acc[j].z);
            acc[j].w = fmaf(a.y, w1.w, acc[j].w);
            acc[j].x = fmaf(a.z, w2.x, acc[j].x);
            acc[j].y = fmaf(a.z, w2.y, acc[j].y);
            acc[j].z = fmaf(a.z, w2.z, acc[j].z);
            acc[j].w = fmaf(a.z, w2.w, acc[j].w);
            acc[j].x = fmaf(a.w, w3.x, acc[j].x);
            acc[j].y = fmaf(a.w, w3.y, acc[j].y);
            acc[j].z = fmaf(a.w, w3.z, acc[j].z);
            acc[j].w = fmaf(a.w, w3.w, acc[j].w);
        }
    }

    // epilogue: bias, relu, store (+stats, +zero aggr)
    const float4 bv = reinterpret_cast<const float4*>(bias)[tx];
    float4 ls = make_float4(0, 0, 0, 0), lss = make_float4(0, 0, 0, 0);
#pragma unroll
    for (int j = 0; j < 8; j++) {
        size_t row = row0 + ty * 8 + j;
        if (row >= N_NODES) break;
        float4 o;
        o.x = fmaxf(acc[j].x + bv.x, 0.0f);
        o.y = fmaxf(acc[j].y + bv.y, 0.0f);
        o.z = fmaxf(acc[j].z + bv.z, 0.0f);
        o.w = fmaxf(acc[j].w + bv.w, 0.0f);
        reinterpret_cast<float4*>(out + row * 64)[tx] = o;
        if (ZEROA)
            reinterpret_cast<float4*>(g_aggr + row * 64)[tx] = make_float4(0, 0, 0, 0);
        if (STATS) {
            ls.x += o.x; ls.y += o.y; ls.z += o.z; ls.w += o.w;
            lss.x += o.x * o.x; lss.y += o.y * o.y;
            lss.z += o.z * o.z; lss.w += o.w * o.w;
        }
    }

    if (STATS) {
        atomicAdd(&sSum[tx * 4 + 0], ls.x);
        atomicAdd(&sSum[tx * 4 + 1], ls.y);
        atomicAdd(&sSum[tx * 4 + 2], ls.z);
        atomicAdd(&sSum[tx * 4 + 3], ls.w);
        atomicAdd(&sSq[tx * 4 + 0], lss.x);
        atomicAdd(&sSq[tx * 4 + 1], lss.y);
        atomicAdd(&sSq[tx * 4 + 2], lss.z);
        atomicAdd(&sSq[tx * 4 + 3], lss.w);
        __syncthreads();
        if (tid < HID) {
            atomicAdd(&stats_out[tid],       sSum[tid]);
            atomicAdd(&stats_out[HID + tid], sSq[tid]);
        }
    }
}

// ---------------- pool with final BN fused ----------------
__global__ __launch_bounds__(256)
void pool_bn_kernel(const float* __restrict__ h,
                    const int* __restrict__ batch,
                    const float* __restrict__ stats,
                    const float* __restrict__ gamma,
                    const float* __restrict__ beta) {
    __shared__ float sc[HID], sh[HID];
    bn_coeffs(stats, gamma, beta, sc, sh);
    __syncthreads();
    int idx = blockIdx.x * blockDim.x + threadIdx.x;
    if (idx >= N_NODES * 16) return;
    int n = idx >> 4, q = idx & 15;
    int g = batch[n];
    float4 v = reinterpret_cast<const float4*>(h)[idx];
    int f = q * 4;
    v.x = v.x * sc[f    ] + sh[f    ];
    v.y = v.y * sc[f + 1] + sh[f + 1];
    v.z = v.z * sc[f + 2] + sh[f + 2];
    v.w = v.w * sc[f + 3] + sh[f + 3];
    atomicAdd(reinterpret_cast<float4*>(g_pool) + (size_t)g * 16 + q, v);
    if (q == 0) atomicAdd(&g_cnt[g], 1.0f);
}

// ---------------- readout MLP: mean -> [64,10] relu -> [10,1] ----------------
__global__ void readout_kernel(const float* __restrict__ Wf1,
                               const float* __restrict__ bf1,
                               const float* __restrict__ Wf2,
                               const float* __restrict__ bf2,
                               float* __restrict__ out) {
    int g = blockIdx.x * blockDim.x + threadIdx.x;
    if (g >= G_GRAPHS) return;
    float inv = 1.0f / fmaxf(g_cnt[g], 1.0f);
    float hid[10];
#pragma unroll
    for (int j = 0; j < 10; j++) hid[j] = bf1[j];
    for (int k = 0; k < 64; k++) {
        float p = g_pool[(size_t)g * 64 + k] * inv;
#pragma unroll
        for (int j = 0; j < 10; j++) hid[j] += p * Wf1[k * 10 + j];
    }
    float o = bf2[0];
#pragma unroll
    for (int j = 0; j < 10; j++) o += fmaxf(hid[j], 0.0f) * Wf2[j];
    out[g] = o;
}

// ---------------- host launcher ----------------
static inline int cdiv(long long a, int b) { return (int)((a + b - 1) / b); }

extern "C" void kernel_launch(void* const* d_in, const int* in_sizes, int n_in,
                              void* d_out, int out_size) {
    (void)in_sizes; (void)n_in; (void)out_size;
    const float* x     = (const float*)d_in[0];
    const int*   ei    = (const int*)  d_in[1];
    const int*   batch = (const int*)  d_in[2];
    const float* W1a = (const float*)d_in[3];  const float* b1a = (const float*)d_in[4];
    const float* W1b = (const float*)d_in[5];  const float* b1b = (const float*)d_in[6];
    const float* e1  = (const float*)d_in[7];
    const float* g1  = (const float*)d_in[8];  const float* be1 = (const float*)d_in[9];
    const float* W2a = (const float*)d_in[10]; const float* b2a = (const float*)d_in[11];
    const float* W2b = (const float*)d_in[12]; const float* b2b = (const float*)d_in[13];
    const float* e2  = (const float*)d_in[14];
    const float* g2  = (const float*)d_in[15]; const float* be2 = (const float*)d_in[16];
    const float* W3a = (const float*)d_in[17]; const float* b3a = (const float*)d_in[18];
    const float* W3b = (const float*)d_in[19]; const float* b3b = (const float*)d_in[20];
    const float* e3  = (const float*)d_in[21];
    const float* g3  = (const float*)d_in[22]; const float* be3 = (const float*)d_in[23];
    const float* Wf1 = (const float*)d_in[24]; const float* bf1 = (const float*)d_in[25];
    const float* Wf2 = (const float*)d_in[26]; const float* bf2 = (const float*)d_in[27];
    float* out = (float*)d_out;

    const int* src = ei;
    const int* dst = ei + N_EDGES;

    void *p_h1, *p_h2, *p_stats;
    cudaGetSymbolAddress(&p_h1, g_h1);
    cudaGetSymbolAddress(&p_h2, g_h2);
    cudaGetSymbolAddress(&p_stats, g_stats);
    float* h1 = (float*)p_h1;
    float* h2 = (float*)p_h2;
    float* st0 = (float*)p_stats;
    float* st1 = st0 + 2 * HID;
    float* st2 = st0 + 4 * HID;

    const int TB = 256;
    const int GB = cdiv(N_NODES, TROWS);   // 782

    zero_misc_kernel<<<cdiv(N_NODES * F_IN, TB), TB>>>();

    // ===== layer 1 =====
    scatter16_kernel<<<cdiv((long long)N_EDGES * 4, TB), TB>>>(x, src, dst);
    gemm_kernel<F_IN, true,  false, false, false><<<GB, TB>>>(x,  W1a, b1a, e1, nullptr, nullptr, nullptr, h1, nullptr);
    gemm_kernel<HID,  false, false, true,  true ><<<GB, TB>>>(h1, W1b, b1b, nullptr, nullptr, nullptr, nullptr, h2, st0);

    // ===== layer 2 =====
    scatter_bn_kernel<<<cdiv((long long)N_EDGES * 16, TB), TB>>>(h2, src, dst, st0, g1, be1);
    gemm_kernel<HID, true,  true,  false, false><<<GB, TB>>>(h2, W2a, b2a, e2, st0, g1, be1, h1, nullptr);
    gemm_kernel<HID, false, false, true,  true ><<<GB, TB>>>(h1, W2b, b2b, nullptr, nullptr, nullptr, nullptr, h2, st1);

    // ===== layer 3 =====
    scatter_bn_kernel<<<cdiv((long long)N_EDGES * 16, TB), TB>>>(h2, src, dst, st1, g2, be2);
    gemm_kernel<HID, true,  true,  false, false><<<GB, TB>>>(h2, W3a, b3a, e3, st1, g2, be2, h1, nullptr);
    gemm_kernel<HID, false, false, true,  false><<<GB, TB>>>(h1, W3b, b3b, nullptr, nullptr, nullptr, nullptr, h2, st2);

    // ===== pool + readout (BN3 fused into pool) =====
    pool_bn_kernel<<<cdiv(N_NODES * 16, TB), TB>>>(h2, batch, st2, g3, be3);
    readout_kernel<<<cdiv(G_GRAPHS, TB), TB>>>(Wf1, bf1, Wf2, bf2, out);
}

// round 4
// speedup vs baseline: 1.8894x; 1.2684x over previous
#include <cuda_runtime.h>
#include <cuda_bf16.h>
#include <cstddef>

#define N_NODES 100000
#define N_EDGES 1200000
#define HID 64
#define F_IN 16
#define G_GRAPHS 1024
#define TROWS 128
#define CAP 96            // max in-degree capacity (Poisson(12): overflow prob ~1e-26)

// ---------------- scratch (device globals; no allocation) ----------------
__device__ float g_c1  [(size_t)N_NODES * F_IN];
__device__ float g_h1  [(size_t)N_NODES * HID];
__device__ float g_h2  [(size_t)N_NODES * HID];
__device__ int   g_deg [N_NODES];
__device__ int   g_bucket[(size_t)N_NODES * CAP];
__device__ float g_stats[3][2 * HID];
__device__ float g_pool[(size_t)G_GRAPHS * HID];
__device__ float g_cnt [G_GRAPHS];

// BN scale/shift from accumulated sum/sumsq (training-mode batch stats)
__device__ __forceinline__ void bn_coeffs(const float* __restrict__ stats,
                                          const float* __restrict__ gamma,
                                          const float* __restrict__ beta,
                                          float* sc, float* sh) {
    int t = threadIdx.x;
    if (t < HID) {
        const float invN = 1.0f / (float)N_NODES;
        float mean = stats[t] * invN;
        float var  = stats[HID + t] * invN - mean * mean;
        float s    = gamma[t] * rsqrtf(var + 1e-5f);
        sc[t] = s;
        sh[t] = beta[t] - mean * s;
    }
}

// ---------------- zero pass ----------------
__global__ void zero_misc_kernel() {
    int i = blockIdx.x * blockDim.x + threadIdx.x;
    if (i < N_NODES)         g_deg[i] = 0;
    if (i < 3 * 2 * HID)     ((float*)g_stats)[i] = 0.0f;
    if (i < G_GRAPHS * HID)  g_pool[i] = 0.0f;
    if (i < G_GRAPHS)        g_cnt[i]  = 0.0f;
}

// ---------------- bucket build (once per launch, reused by all 3 layers) ----------------
__global__ __launch_bounds__(256)
void bucket_kernel(const int* __restrict__ src, const int* __restrict__ dst) {
    int e = blockIdx.x * blockDim.x + threadIdx.x;
    if (e >= N_EDGES) return;
    int d = dst[e];
    int pos = atomicAdd(&g_deg[d], 1);
    if (pos < CAP) g_bucket[(size_t)d * CAP + pos] = src[e];
}

// ---------------- layer-1 gather-aggregate (16-wide, no BN) ----------------
// 4 threads per node; each owns 4 cols (float4). out = (1+eps)*x_n + sum x_j
__global__ __launch_bounds__(256)
void aggr16_kernel(const float* __restrict__ x,
                   const float* __restrict__ eps_p,
                   float* __restrict__ out) {
    int idx = blockIdx.x * blockDim.x + threadIdx.x;
    if (idx >= N_NODES * 4) return;
    int n = idx >> 2, q = idx & 3;
    int deg = min(g_deg[n], CAP);
    float epsv = 1.0f + *eps_p;
    float4 v = reinterpret_cast<const float4*>(x + (size_t)n * F_IN)[q];
    float4 a0 = make_float4(epsv * v.x, epsv * v.y, epsv * v.z, epsv * v.w);
    float4 a1 = make_float4(0, 0, 0, 0);
    const int* bk = g_bucket + (size_t)n * CAP;
    int i = 0;
    for (; i + 2 <= deg; i += 2) {
        int s0 = bk[i], s1 = bk[i + 1];
        float4 m0 = reinterpret_cast<const float4*>(x + (size_t)s0 * F_IN)[q];
        float4 m1 = reinterpret_cast<const float4*>(x + (size_t)s1 * F_IN)[q];
        a0.x += m0.x; a0.y += m0.y; a0.z += m0.z; a0.w += m0.w;
        a1.x += m1.x; a1.y += m1.y; a1.z += m1.z; a1.w += m1.w;
    }
    if (i < deg) {
        int s0 = bk[i];
        float4 m0 = reinterpret_cast<const float4*>(x + (size_t)s0 * F_IN)[q];
        a0.x += m0.x; a0.y += m0.y; a0.z += m0.z; a0.w += m0.w;
    }
    a0.x += a1.x; a0.y += a1.y; a0.z += a1.z; a0.w += a1.w;
    reinterpret_cast<float4*>(out + (size_t)n * F_IN)[q] = a0;
}

// ---------------- 64-wide gather-aggregate with BN fused ----------------
// One warp per node; lane owns cols {2l, 2l+1}.
// out[n] = (1+eps)*BN(h[n]) + sum_{j in in(n)} BN(h[j])
__global__ __launch_bounds__(256)
void aggr64_kernel(const float* __restrict__ h,
                   const float* __restrict__ stats,
                   const float* __restrict__ gamma,
                   const float* __restrict__ beta,
                   const float* __restrict__ eps_p,
                   float* __restrict__ out) {
    __shared__ float sc[HID], sh[HID];
    bn_coeffs(stats, gamma, beta, sc, sh);
    __syncthreads();

    int gw = (blockIdx.x * blockDim.x + threadIdx.x) >> 5;
    if (gw >= N_NODES) return;
    int lane = threadIdx.x & 31;
    float2 scl = *reinterpret_cast<const float2*>(&sc[2 * lane]);
    float2 shf = *reinterpret_cast<const float2*>(&sh[2 * lane]);

    int deg = min(g_deg[gw], CAP);
    float epsv = 1.0f + *eps_p;

    float2 v = reinterpret_cast<const float2*>(h + (size_t)gw * HID)[lane];
    float2 a0, a1 = {0, 0}, a2 = {0, 0}, a3 = {0, 0};
    a0.x = epsv * fmaf(v.x, scl.x, shf.x);
    a0.y = epsv * fmaf(v.y, scl.y, shf.y);

    const int* bk = g_bucket + (size_t)gw * CAP;
    for (int base = 0; base < deg; base += 32) {
        int cnt = min(32, deg - base);
        int s = 0;
        if (lane < cnt) s = bk[base + lane];
        int i = 0;
        for (; i + 4 <= cnt; i += 4) {
            int s0 = __shfl_sync(0xffffffffu, s, i);
            int s1 = __shfl_sync(0xffffffffu, s, i + 1);
            int s2 = __shfl_sync(0xffffffffu, s, i + 2);
            int s3 = __shfl_sync(0xffffffffu, s, i + 3);
            float2 m0 = reinterpret_cast<const float2*>(h + (size_t)s0 * HID)[lane];
            float2 m1 = reinterpret_cast<const float2*>(h + (size_t)s1 * HID)[lane];
            float2 m2 = reinterpret_cast<const float2*>(h + (size_t)s2 * HID)[lane];
            float2 m3 = reinterpret_cast<const float2*>(h + (size_t)s3 * HID)[lane];
            a0.x += fmaf(m0.x, scl.x, shf.x); a0.y += fmaf(m0.y, scl.y, shf.y);
            a1.x += fmaf(m1.x, scl.x, shf.x); a1.y += fmaf(m1.y, scl.y, shf.y);
            a2.x += fmaf(m2.x, scl.x, shf.x); a2.y += fmaf(m2.y, scl.y, shf.y);
            a3.x += fmaf(m3.x, scl.x, shf.x); a3.y += fmaf(m3.y, scl.y, shf.y);
        }
        for (; i < cnt; i++) {
            int s0 = __shfl_sync(0xffffffffu, s, i);
            float2 m0 = reinterpret_cast<const float2*>(h + (size_t)s0 * HID)[lane];
            a0.x += fmaf(m0.x, scl.x, shf.x); a0.y += fmaf(m0.y, scl.y, shf.y);
        }
    }
    a0.x += a1.x + a2.x + a3.x;
    a0.y += a1.y + a2.y + a3.y;
    reinterpret_cast<float2*>(out + (size_t)gw * HID)[lane] = a0;
}

// ---------------- GEMM [N,K]@[K,64] + bias + ReLU ----------------
// 256 threads, tile 128x64, 8 rows x 4 cols per thread, k-vectorized by 4.
// STATS: accumulate per-column sum/sumsq of output into stats_out.
template <int K, bool STATS>
__global__ __launch_bounds__(256, 3)
void gemm_kernel(const float* __restrict__ X,
                 const float* __restrict__ W,
                 const float* __restrict__ bias,
                 float* __restrict__ out,
                 float* __restrict__ stats_out) {
    __shared__ float sW[K * 64];
    __shared__ float sIn[TROWS * K];
    __shared__ float sSum[HID], sSq[HID];

    const int tid = threadIdx.x;
    const int tx  = tid & 15;
    const int ty  = tid >> 4;
    const size_t row0 = (size_t)blockIdx.x * TROWS;

    if (STATS && tid < HID) { sSum[tid] = 0.0f; sSq[tid] = 0.0f; }

    for (int i = tid; i < K * 64; i += 256) sW[i] = W[i];

    for (int i = tid; i < TROWS * K; i += 256) {
        size_t r = row0 + (size_t)(i / K);
        sIn[i] = (r < N_NODES) ? X[row0 * K + i] : 0.0f;
    }
    __syncthreads();

    float4 acc[8];
#pragma unroll
    for (int j = 0; j < 8; j++) acc[j] = make_float4(0, 0, 0, 0);

#pragma unroll
    for (int k = 0; k < K; k += 4) {
        float4 w0 = *reinterpret_cast<const float4*>(&sW[(k + 0) * 64 + tx * 4]);
        float4 w1 = *reinterpret_cast<const float4*>(&sW[(k + 1) * 64 + tx * 4]);
        float4 w2 = *reinterpret_cast<const float4*>(&sW[(k + 2) * 64 + tx * 4]);
        float4 w3 = *reinterpret_cast<const float4*>(&sW[(k + 3) * 64 + tx * 4]);
#pragma unroll
        for (int j = 0; j < 8; j++) {
            float4 a = *reinterpret_cast<const float4*>(&sIn[(ty * 8 + j) * K + k]);
            acc[j].x = fmaf(a.x, w0.x, acc[j].x);
            acc[j].y = fmaf(a.x, w0.y, acc[j].y);
            acc[j].z = fmaf(a.x, w0.z, acc[j].z);
            acc[j].w = fmaf(a.x, w0.w, acc[j].w);
            acc[j].x = fmaf(a.y, w1.x, acc[j].x);
            acc[j].y = fmaf(a.y, w1.y, acc[j].y);
            acc[j].z = fmaf(a.y, w1.z, acc[j].z);
            acc[j].w = fmaf(a.y, w1.w, acc[j].w);
            acc[j].x = fmaf(a.z, w2.x, acc[j].x);
            acc[j].y = fmaf(a.z, w2.y, acc[j].y);
            acc[j].z = fmaf(a.z, w2.z, acc[j].z);
            acc[j].w = fmaf(a.z, w2.w, acc[j].w);
            acc[j].x = fmaf(a.w, w3.x, acc[j].x);
            acc[j].y = fmaf(a.w, w3.y, acc[j].y);
            acc[j].z = fmaf(a.w, w3.z, acc[j].z);
            acc[j].w = fmaf(a.w, w3.w, acc[j].w);
        }
    }

    const float4 bv = reinterpret_cast<const float4*>(bias)[tx];
    float4 ls = make_float4(0, 0, 0, 0), lss = make_float4(0, 0, 0, 0);
#pragma unroll
    for (int j = 0; j < 8; j++) {
        size_t row = row0 + ty * 8 + j;
        if (row >= N_NODES) break;
        float4 o;
        o.x = fmaxf(acc[j].x + bv.x, 0.0f);
        o.y = fmaxf(acc[j].y + bv.y, 0.0f);
        o.z = fmaxf(acc[j].z + bv.z, 0.0f);
        o.w = fmaxf(acc[j].w + bv.w, 0.0f);
        reinterpret_cast<float4*>(out + row * 64)[tx] = o;
        if (STATS) {
            ls.x += o.x; ls.y += o.y; ls.z += o.z; ls.w += o.w;
            lss.x += o.x * o.x; lss.y += o.y * o.y;
            lss.z += o.z * o.z; lss.w += o.w * o.w;
        }
    }

    if (STATS) {
        atomicAdd(&sSum[tx * 4 + 0], ls.x);
        atomicAdd(&sSum[tx * 4 + 1], ls.y);
        atomicAdd(&sSum[tx * 4 + 2], ls.z);
        atomicAdd(&sSum[tx * 4 + 3], ls.w);
        atomicAdd(&sSq[tx * 4 + 0], lss.x);
        atomicAdd(&sSq[tx * 4 + 1], lss.y);
        atomicAdd(&sSq[tx * 4 + 2], lss.z);
        atomicAdd(&sSq[tx * 4 + 3], lss.w);
        __syncthreads();
        if (tid < HID) {
            atomicAdd(&stats_out[tid],       sSum[tid]);
            atomicAdd(&stats_out[HID + tid], sSq[tid]);
        }
    }
}

// ---------------- pool with final BN fused ----------------
__global__ __launch_bounds__(256)
void pool_bn_kernel(const float* __restrict__ h,
                    const int* __restrict__ batch,
                    const float* __restrict__ stats,
                    const float* __restrict__ gamma,
                    const float* __restrict__ beta) {
    __shared__ float sc[HID], sh[HID];
    bn_coeffs(stats, gamma, beta, sc, sh);
    __syncthreads();
    int idx = blockIdx.x * blockDim.x + threadIdx.x;
    if (idx >= N_NODES * 16) return;
    int n = idx >> 4, q = idx & 15;
    int g = batch[n];
    float4 v = reinterpret_cast<const float4*>(h)[idx];
    int f = q * 4;
    v.x = v.x * sc[f    ] + sh[f    ];
    v.y = v.y * sc[f + 1] + sh[f + 1];
    v.z = v.z * sc[f + 2] + sh[f + 2];
    v.w = v.w * sc[f + 3] + sh[f + 3];
    atomicAdd(reinterpret_cast<float4*>(g_pool) + (size_t)g * 16 + q, v);
    if (q == 0) atomicAdd(&g_cnt[g], 1.0f);
}

// ---------------- readout MLP: mean -> [64,10] relu -> [10,1] ----------------
__global__ void readout_kernel(const float* __restrict__ Wf1,
                               const float* __restrict__ bf1,
                               const float* __restrict__ Wf2,
                               const float* __restrict__ bf2,
                               float* __restrict__ out) {
    int g = blockIdx.x * blockDim.x + threadIdx.x;
    if (g >= G_GRAPHS) return;
    float inv = 1.0f / fmaxf(g_cnt[g], 1.0f);
    float hid[10];
#pragma unroll
    for (int j = 0; j < 10; j++) hid[j] = bf1[j];
    for (int k = 0; k < 64; k++) {
        float p = g_pool[(size_t)g * 64 + k] * inv;
#pragma unroll
        for (int j = 0; j < 10; j++) hid[j] += p * Wf1[k * 10 + j];
    }
    float o = bf2[0];
#pragma unroll
    for (int j = 0; j < 10; j++) o += fmaxf(hid[j], 0.0f) * Wf2[j];
    out[g] = o;
}

// ---------------- host launcher ----------------
static inline int cdiv(long long a, int b) { return (int)((a + b - 1) / b); }

extern "C" void kernel_launch(void* const* d_in, const int* in_sizes, int n_in,
                              void* d_out, int out_size) {
    (void)in_sizes; (void)n_in; (void)out_size;
    const float* x     = (const float*)d_in[0];
    const int*   ei    = (const int*)  d_in[1];
    const int*   batch = (const int*)  d_in[2];
    const float* W1a = (const float*)d_in[3];  const float* b1a = (const float*)d_in[4];
    const float* W1b = (const float*)d_in[5];  const float* b1b = (const float*)d_in[6];
    const float* e1  = (const float*)d_in[7];
    const float* g1  = (const float*)d_in[8];  const float* be1 = (const float*)d_in[9];
    const float* W2a = (const float*)d_in[10]; const float* b2a = (const float*)d_in[11];
    const float* W2b = (const float*)d_in[12]; const float* b2b = (const float*)d_in[13];
    const float* e2  = (const float*)d_in[14];
    const float* g2  = (const float*)d_in[15]; const float* be2 = (const float*)d_in[16];
    const float* W3a = (const float*)d_in[17]; const float* b3a = (const float*)d_in[18];
    const float* W3b = (const float*)d_in[19]; const float* b3b = (const float*)d_in[20];
    const float* e3  = (const float*)d_in[21];
    const float* g3  = (const float*)d_in[22]; const float* be3 = (const float*)d_in[23];
    const float* Wf1 = (const float*)d_in[24]; const float* bf1 = (const float*)d_in[25];
    const float* Wf2 = (const float*)d_in[26]; const float* bf2 = (const float*)d_in[27];
    float* out = (float*)d_out;

    const int* src = ei;
    const int* dst = ei + N_EDGES;

    void *p_c1, *p_h1, *p_h2, *p_stats;
    cudaGetSymbolAddress(&p_c1, g_c1);
    cudaGetSymbolAddress(&p_h1, g_h1);
    cudaGetSymbolAddress(&p_h2, g_h2);
    cudaGetSymbolAddress(&p_stats, g_stats);
    float* c1 = (float*)p_c1;
    float* h1 = (float*)p_h1;
    float* h2 = (float*)p_h2;
    float* st0 = (float*)p_stats;
    float* st1 = st0 + 2 * HID;
    float* st2 = st0 + 4 * HID;

    const int TB = 256;
    const int GB = cdiv(N_NODES, TROWS);   // 782

    zero_misc_kernel<<<cdiv(N_NODES, TB), TB>>>();
    bucket_kernel<<<cdiv(N_EDGES, TB), TB>>>(src, dst);

    // ===== layer 1 =====
    aggr16_kernel<<<cdiv(N_NODES * 4, TB), TB>>>(x, e1, c1);
    gemm_kernel<F_IN, false><<<GB, TB>>>(c1, W1a, b1a, h1, nullptr);
    gemm_kernel<HID,  true ><<<GB, TB>>>(h1, W1b, b1b, h2, st0);

    // ===== layer 2 =====
    aggr64_kernel<<<cdiv(N_NODES * 32, TB), TB>>>(h2, st0, g1, be1, e2, h1);
    gemm_kernel<HID, false><<<GB, TB>>>(h1, W2a, b2a, h2, nullptr);
    gemm_kernel<HID, true ><<<GB, TB>>>(h2, W2b, b2b, h1, st1);

    // ===== layer 3 =====
    aggr64_kernel<<<cdiv(N_NODES * 32, TB), TB>>>(h1, st1, g2, be2, e3, h2);
    gemm_kernel<HID, false><<<GB, TB>>>(h2, W3a, b3a, h1, nullptr);
    gemm_kernel<HID, true ><<<GB, TB>>>(h1, W3b, b3b, h2, st2);

    // ===== pool + readout (BN3 fused into pool) =====
    pool_bn_kernel<<<cdiv(N_NODES * 16, TB), TB>>>(h2, batch, st2, g3, be3);
    readout_kernel<<<cdiv(G_GRAPHS, TB), TB>>>(Wf1, bf1, Wf2, bf2, out);
}